// round 6
// baseline (speedup 1.0000x reference)
#include <cuda_runtime.h>
#include <cuda_bf16.h>
#include <math.h>
#include <stdint.h>

#define NN   50000
#define EE   800000
#define INF  64
#define OUTF 64
#define KH   256      // HID*IN
#define KTOT 320      // KH + IN
#define NKC  20       // K chunks of 16

// ---------------------------------------------------------------------------
// Scratch (__device__ globals)
// ---------------------------------------------------------------------------
__device__ int    g_deg[NN];
__device__ int    g_rowstart[NN + 1];
__device__ int    g_cursor[NN];
__device__ float4 g_ws[EE];                    // {wsx, wsy, wsz, bitcast(src)}
__device__ uint4  g_Wfrag[NKC * 8 * 32];       // prepacked B frags {Bh0,Bh1,Bl0,Bl1}
__device__ float  g_bsum[OUTF];                // b_neigh + bias
__device__ __nv_bfloat16 g_Ah[(size_t)NN * KTOT];   // A hi (mean-scaled neigh | feat)
__device__ __nv_bfloat16 g_Al[(size_t)NN * KTOT];   // A lo residual

// ---------------------------------------------------------------------------
// helpers
// ---------------------------------------------------------------------------
#define MMA_BF16(d, a0, a1, a2, a3, b0, b1)                                   \
    asm volatile("mma.sync.aligned.m16n8k16.row.col.f32.bf16.bf16.f32 "       \
                 "{%0,%1,%2,%3}, {%4,%5,%6,%7}, {%8,%9}, {%0,%1,%2,%3};"      \
                 : "+f"((d)[0]), "+f"((d)[1]), "+f"((d)[2]), "+f"((d)[3])     \
                 : "r"(a0), "r"(a1), "r"(a2), "r"(a3), "r"(b0), "r"(b1))

__device__ __forceinline__ uint64_t pk2(float lo, float hi) {
    uint64_t r;
    asm("mov.b64 %0, {%1, %2};" : "=l"(r) : "f"(lo), "f"(hi));
    return r;
}
__device__ __forceinline__ void upk2(uint64_t v, float& lo, float& hi) {
    asm("mov.b64 {%0, %1}, %2;" : "=f"(lo), "=f"(hi) : "l"(v));
}
__device__ __forceinline__ uint64_t fma2(uint64_t a, uint64_t b, uint64_t c) {
    uint64_t d;
    asm("fma.rn.f32x2 %0, %1, %2, %3;" : "=l"(d) : "l"(a), "l"(b), "l"(c));
    return d;
}
__device__ __forceinline__ uint64_t mul2(uint64_t a, uint64_t b) {
    uint64_t d;
    asm("mul.rn.f32x2 %0, %1, %2;" : "=l"(d) : "l"(a), "l"(b));
    return d;
}
__device__ __forceinline__ uint64_t and64(uint64_t a, uint64_t b) {
    uint64_t d;
    asm("and.b64 %0, %1, %2;" : "=l"(d) : "l"(a), "l"(b));
    return d;
}
// pack two f32 -> bf16x2 {lo16=a, hi16=b}
__device__ __forceinline__ uint32_t cvt_bf2(float a, float b) {
    uint32_t r;
    asm("cvt.rn.bf16x2.f32 %0, %1, %2;" : "=r"(r) : "f"(b), "f"(a));
    return r;
}
__device__ __forceinline__ uint32_t pk_hi(float2 v, float2& res) {
    __nv_bfloat162 h = __float22bfloat162_rn(v);
    float2 hf = __bfloat1622float2(h);
    res = make_float2(v.x - hf.x, v.y - hf.y);
    return *reinterpret_cast<uint32_t*>(&h);
}
__device__ __forceinline__ uint32_t pkb(float2 v) {
    __nv_bfloat162 h = __float22bfloat162_rn(v);
    return *reinterpret_cast<uint32_t*>(&h);
}

// ---------------------------------------------------------------------------
// 1) Degree histogram
// ---------------------------------------------------------------------------
__global__ void hist_kernel(const int* __restrict__ dst)
{
    int e = blockIdx.x * blockDim.x + threadIdx.x;
    if (e < EE) atomicAdd(&g_deg[__ldg(&dst[e])], 1);
}

// ---------------------------------------------------------------------------
// 1b) Weight prep: per-thread mma B fragments (bf16 hi/lo), plus bsum.
// ---------------------------------------------------------------------------
__global__ void wprep_kernel(const float* __restrict__ W_self,
                             const float* __restrict__ W_neigh,
                             const float* __restrict__ b_neigh,
                             const float* __restrict__ bias)
{
    int idx = blockIdx.x * blockDim.x + threadIdx.x;
    if (idx < OUTF) g_bsum[idx] = __ldg(&b_neigh[idx]) + __ldg(&bias[idx]);
    if (idx >= NKC * 8 * 32) return;

    const int lane = idx & 31;
    const int nc   = (idx >> 5) & 7;
    const int kc   = idx >> 8;
    const int n    = nc * 8 + (lane >> 2);
    const int k0   = kc * 16 + (lane & 3) * 2;

    float v[4];
#pragma unroll
    for (int r = 0; r < 2; r++)
#pragma unroll
        for (int j = 0; j < 2; j++) {
            const int k = k0 + r * 8 + j;
            v[r * 2 + j] = (k < KH) ? __ldg(&W_neigh[(size_t)n * KH + k])
                                    : __ldg(&W_self[(size_t)n * INF + (k - KH)]);
        }

    float2 r0, r1;
    uint4 q;
    q.x = pk_hi(make_float2(v[0], v[1]), r0);
    q.y = pk_hi(make_float2(v[2], v[3]), r1);
    q.z = pkb(r0);
    q.w = pkb(r1);
    g_Wfrag[idx] = q;
}

// ---------------------------------------------------------------------------
// 2) Exclusive prefix sum over degrees (single block)
// ---------------------------------------------------------------------------
__global__ void scan_kernel()
{
    __shared__ int partial[1024];
    const int T = 1024;
    const int chunk = (NN + T - 1) / T;
    const int t = threadIdx.x;
    const int base = t * chunk;

    int sum = 0;
    for (int i = 0; i < chunk; i++) {
        int idx = base + i;
        if (idx < NN) sum += g_deg[idx];
    }
    partial[t] = sum;
    __syncthreads();
    for (int off = 1; off < T; off <<= 1) {
        int v = 0;
        if (t >= off) v = partial[t - off];
        __syncthreads();
        partial[t] += v;
        __syncthreads();
    }
    int run = (t > 0) ? partial[t - 1] : 0;
    for (int i = 0; i < chunk; i++) {
        int idx = base + i;
        if (idx < NN) {
            g_rowstart[idx] = run;
            g_cursor[idx]   = run;
            run += g_deg[idx];
        }
    }
    if (t == T - 1) g_rowstart[NN] = run;
}

// ---------------------------------------------------------------------------
// 3) Scatter edges into CSR buckets with precomputed spatial weights
// ---------------------------------------------------------------------------
__global__ void __launch_bounds__(256) scatter_kernel(
    const float* __restrict__ pos,
    const int*   __restrict__ src,
    const int*   __restrict__ dst)
{
    int e = blockIdx.x * blockDim.x + threadIdx.x;
    if (e >= EE) return;
    const int s = __ldg(&src[e]);
    const int d = __ldg(&dst[e]);

    const float rx = __ldg(&pos[d * 3 + 0]) - __ldg(&pos[s * 3 + 0]);
    const float ry = __ldg(&pos[d * 3 + 1]) - __ldg(&pos[s * 3 + 1]);
    const float rz = __ldg(&pos[d * 3 + 2]) - __ldg(&pos[s * 3 + 2]);
    const float scal = sqrtf(fmaf(rx, rx, fmaf(ry, ry, rz * rz))) + 1e-7f;
    const float inv  = __fdividef(1.0f, scal);

    const int p = atomicAdd(&g_cursor[d], 1);
    g_ws[p] = make_float4((rx + 1.0f) * inv, (ry + 1.0f) * inv,
                          (rz + 1.0f) * inv, __int_as_float(s));
}

// ---------------------------------------------------------------------------
// 4) Aggregate: warp per node, lane owns 8 channels as 4 f32x2 pairs.
//    Packed FFMA2 math; leaky(x) = 0.505x + 0.495|x| (branch-free, exact).
//    Emits bf16 hi/lo A rows directly (incl. feat columns at k>=256).
// ---------------------------------------------------------------------------
__global__ void __launch_bounds__(256) aggregate_kernel(
    const float* __restrict__ feat,
    const float* __restrict__ W_sp,
    const float* __restrict__ b_sp)
{
    const int lane = threadIdx.x & 31;
    const int node = (blockIdx.x * blockDim.x + threadIdx.x) >> 5;
    if (node >= NN) return;
    const int k0 = lane * 8;

    const uint64_t ABSM = 0x7FFFFFFF7FFFFFFFULL;
    const uint64_t C505 = pk2(0.505f, 0.505f);
    const uint64_t C495 = pk2(0.495f, 0.495f);

    uint64_t w0p[4], w1p[4], w2p[4], bbp[4];
#pragma unroll
    for (int p = 0; p < 4; p++) {
        const int k = k0 + 2 * p;
        w0p[p] = pk2(__ldg(&W_sp[k * 3 + 0]), __ldg(&W_sp[(k + 1) * 3 + 0]));
        w1p[p] = pk2(__ldg(&W_sp[k * 3 + 1]), __ldg(&W_sp[(k + 1) * 3 + 1]));
        w2p[p] = pk2(__ldg(&W_sp[k * 3 + 2]), __ldg(&W_sp[(k + 1) * 3 + 2]));
        bbp[p] = pk2(__ldg(&b_sp[k]),         __ldg(&b_sp[k + 1]));
    }

    const int start = g_rowstart[node];
    const int end   = g_rowstart[node + 1];

    uint64_t acc[4];
#pragma unroll
    for (int p = 0; p < 4; p++) acc[p] = 0;

    int j = start;
    for (; j + 2 <= end; j += 2) {
        const float4 wa = __ldg(&g_ws[j]);
        const float4 wb = __ldg(&g_ws[j + 1]);
        const int sa = __float_as_int(wa.w);
        const int sb = __float_as_int(wb.w);
        const float2 fa = __ldg(reinterpret_cast<const float2*>(&feat[(size_t)sa * INF + lane * 2]));
        const float2 fb = __ldg(reinterpret_cast<const float2*>(&feat[(size_t)sb * INF + lane * 2]));
        const uint64_t wax = pk2(wa.x, wa.x), way = pk2(wa.y, wa.y), waz = pk2(wa.z, wa.z);
        const uint64_t wbx = pk2(wb.x, wb.x), wby = pk2(wb.y, wb.y), wbz = pk2(wb.z, wb.z);
        const uint64_t fa0 = pk2(fa.x, fa.x), fa1 = pk2(fa.y, fa.y);
        const uint64_t fb0 = pk2(fb.x, fb.x), fb1 = pk2(fb.y, fb.y);
#pragma unroll
        for (int p = 0; p < 4; p++) {
            uint64_t ta = fma2(wax, w0p[p], fma2(way, w1p[p], fma2(waz, w2p[p], bbp[p])));
            uint64_t tb = fma2(wbx, w0p[p], fma2(wby, w1p[p], fma2(wbz, w2p[p], bbp[p])));
            ta = fma2(and64(ta, ABSM), C495, mul2(ta, C505));
            tb = fma2(and64(tb, ABSM), C495, mul2(tb, C505));
            acc[p] = fma2(ta, (p < 2) ? fa0 : fa1, acc[p]);
            acc[p] = fma2(tb, (p < 2) ? fb0 : fb1, acc[p]);
        }
    }
    if (j < end) {
        const float4 wa = __ldg(&g_ws[j]);
        const int sa = __float_as_int(wa.w);
        const float2 fa = __ldg(reinterpret_cast<const float2*>(&feat[(size_t)sa * INF + lane * 2]));
        const uint64_t wax = pk2(wa.x, wa.x), way = pk2(wa.y, wa.y), waz = pk2(wa.z, wa.z);
        const uint64_t fa0 = pk2(fa.x, fa.x), fa1 = pk2(fa.y, fa.y);
#pragma unroll
        for (int p = 0; p < 4; p++) {
            uint64_t ta = fma2(wax, w0p[p], fma2(way, w1p[p], fma2(waz, w2p[p], bbp[p])));
            ta = fma2(and64(ta, ABSM), C495, mul2(ta, C505));
            acc[p] = fma2(ta, (p < 2) ? fa0 : fa1, acc[p]);
        }
    }

    // mean-scale, split to bf16 hi/lo, store one uint4 per matrix
    const float sc = (end > start) ? __fdividef(1.0f, (float)(end - start)) : 0.0f;
    uint32_t hq[4], lq[4];
#pragma unroll
    for (int p = 0; p < 4; p++) {
        float x0, x1;
        upk2(acc[p], x0, x1);
        x0 *= sc; x1 *= sc;
        const uint32_t h = cvt_bf2(x0, x1);
        const float h0 = __uint_as_float(h << 16);
        const float h1 = __uint_as_float(h & 0xFFFF0000u);
        hq[p] = h;
        lq[p] = cvt_bf2(x0 - h0, x1 - h1);
    }
    *reinterpret_cast<uint4*>(&g_Ah[(size_t)node * KTOT + k0]) = make_uint4(hq[0], hq[1], hq[2], hq[3]);
    *reinterpret_cast<uint4*>(&g_Al[(size_t)node * KTOT + k0]) = make_uint4(lq[0], lq[1], lq[2], lq[3]);

    // feat columns [256, 320): 2 values per lane
    const float2 f = __ldg(reinterpret_cast<const float2*>(&feat[(size_t)node * INF + lane * 2]));
    const uint32_t fh = cvt_bf2(f.x, f.y);
    const float fh0 = __uint_as_float(fh << 16);
    const float fh1 = __uint_as_float(fh & 0xFFFF0000u);
    *reinterpret_cast<uint32_t*>(&g_Ah[(size_t)node * KTOT + KH + lane * 2]) = fh;
    *reinterpret_cast<uint32_t*>(&g_Al[(size_t)node * KTOT + KH + lane * 2]) = cvt_bf2(f.x - fh0, f.y - fh1);
}

// ---------------------------------------------------------------------------
// 5) Node GEMM via mma.sync bf16, 3-term hi/lo. A already bf16 in g_Ah/g_Al.
// ---------------------------------------------------------------------------
__global__ void __launch_bounds__(256) gemm_kernel(float* __restrict__ out)
{
    const int lane = threadIdx.x & 31;
    const int warp = threadIdx.x >> 5;
    const int m    = blockIdx.x * 128 + warp * 16 + (lane >> 2);
    const int kq   = (lane & 3) * 2;

    const bool v0 = (m < NN);
    const bool v1 = (m + 8 < NN);

    float D[8][4];
#pragma unroll
    for (int nc = 0; nc < 8; nc++)
#pragma unroll
        for (int i = 0; i < 4; i++) D[nc][i] = 0.0f;

    const size_t r0 = (size_t)m * KTOT;
    const size_t r1 = (size_t)(m + 8) * KTOT;

#pragma unroll 4
    for (int kc = 0; kc < NKC; kc++) {
        const int k = kc * 16 + kq;
        uint32_t ah0 = 0, ah1 = 0, ah2 = 0, ah3 = 0;
        uint32_t al0 = 0, al1 = 0, al2 = 0, al3 = 0;
        if (v0) {
            ah0 = __ldg(reinterpret_cast<const uint32_t*>(&g_Ah[r0 + k]));
            ah2 = __ldg(reinterpret_cast<const uint32_t*>(&g_Ah[r0 + k + 8]));
            al0 = __ldg(reinterpret_cast<const uint32_t*>(&g_Al[r0 + k]));
            al2 = __ldg(reinterpret_cast<const uint32_t*>(&g_Al[r0 + k + 8]));
        }
        if (v1) {
            ah1 = __ldg(reinterpret_cast<const uint32_t*>(&g_Ah[r1 + k]));
            ah3 = __ldg(reinterpret_cast<const uint32_t*>(&g_Ah[r1 + k + 8]));
            al1 = __ldg(reinterpret_cast<const uint32_t*>(&g_Al[r1 + k]));
            al3 = __ldg(reinterpret_cast<const uint32_t*>(&g_Al[r1 + k + 8]));
        }

        const uint4* wf = &g_Wfrag[(kc * 8) * 32 + lane];
#pragma unroll
        for (int nc = 0; nc < 8; nc++) {
            const uint4 b = __ldg(wf + nc * 32);
            MMA_BF16(D[nc], ah0, ah1, ah2, ah3, b.x, b.y);   // Ah * Wh
            MMA_BF16(D[nc], al0, al1, al2, al3, b.x, b.y);   // Al * Wh
            MMA_BF16(D[nc], ah0, ah1, ah2, ah3, b.z, b.w);   // Ah * Wl
        }
    }

#pragma unroll
    for (int nc = 0; nc < 8; nc++) {
        const int n = nc * 8 + kq;
        const float bx = __ldg(&g_bsum[n]);
        const float by = __ldg(&g_bsum[n + 1]);
        if (v0)
            *reinterpret_cast<float2*>(&out[(size_t)m * OUTF + n]) =
                make_float2(D[nc][0] + bx, D[nc][1] + by);
        if (v1)
            *reinterpret_cast<float2*>(&out[(size_t)(m + 8) * OUTF + n]) =
                make_float2(D[nc][2] + bx, D[nc][3] + by);
    }
}

// ---------------------------------------------------------------------------
// Launch
// ---------------------------------------------------------------------------
extern "C" void kernel_launch(void* const* d_in, const int* in_sizes, int n_in,
                              void* d_out, int out_size)
{
    const float* feat    = (const float*)d_in[0];
    const float* pos     = (const float*)d_in[1];
    const int*   src     = (const int*)  d_in[2];
    const int*   dst     = (const int*)  d_in[3];
    const float* W_self  = (const float*)d_in[4];
    const float* W_sp    = (const float*)d_in[5];
    const float* b_sp    = (const float*)d_in[6];
    const float* W_neigh = (const float*)d_in[7];
    const float* b_neigh = (const float*)d_in[8];
    const float* bias    = (const float*)d_in[9];
    float* out = (float*)d_out;

    void* p_deg = nullptr;
    cudaGetSymbolAddress(&p_deg, g_deg);
    cudaMemsetAsync(p_deg, 0, NN * sizeof(int), 0);

    hist_kernel<<<(EE + 255) / 256, 256>>>(dst);
    wprep_kernel<<<(NKC * 8 * 32 + 255) / 256, 256>>>(W_self, W_neigh, b_neigh, bias);
    scan_kernel<<<1, 1024>>>();
    scatter_kernel<<<(EE + 255) / 256, 256>>>(pos, src, dst);
    aggregate_kernel<<<(NN * 32 + 255) / 256, 256>>>(feat, W_sp, b_sp);
    gemm_kernel<<<(NN + 127) / 128, 256>>>(out);
}